// round 5
// baseline (speedup 1.0000x reference)
#include <cuda_runtime.h>
#include <math_constants.h>

#define BB 32
#define CC 64
#define NN 8192
#define SS 64

// ---------------- device scratch (no allocations allowed) ----------------
__device__ float g_yT[(size_t)BB*NN*CC];    // conv output transposed: [b][n][c]
__device__ float g_feaT[(size_t)BB*NN*CC];  // input fea transposed:   [b][n][c]
__device__ float g_nodeloc[BB*SS*3];        // [b*64+s][3]
__device__ int   g_fidx[BB*SS];
__device__ float g_sum[CC];
__device__ float g_sq[CC];
__device__ float g_a[CC];
__device__ float g_c[CC];

// ---------------- K0: zero BN accumulators (graph-replay safe) -----------
__global__ void k_zero() {
    int i = threadIdx.x;
    if (i < CC) { g_sum[i] = 0.f; g_sq[i] = 0.f; }
}

// ---------------- K1: farthest point sampling -----------------------------
__device__ __forceinline__ void amax2(float &v, int &i, float v2, int i2) {
    if (v2 > v || (v2 == v && i2 < i)) { v = v2; i = i2; }
}

__global__ void k_fps(const float* __restrict__ loc) {
    int b = blockIdx.x;
    const float* L = loc + (size_t)b*3*NN;
    int t = threadIdx.x;
    float px[8], py[8], pz[8], pd[8];
#pragma unroll
    for (int j = 0; j < 8; ++j) {
        int n = j*1024 + t;
        px[j] = L[n]; py[j] = L[NN+n]; pz[j] = L[2*NN+n];
        pd[j] = 1e10f;
    }
    __shared__ float swv[32];
    __shared__ int   swi[32];
    __shared__ int   s_far;
    if (t == 0) s_far = 0;
    __syncthreads();
    int lane = t & 31, wid = t >> 5;
    for (int it = 0; it < SS; ++it) {
        int far = s_far;
        if (t == 0) g_fidx[b*SS + it] = far;
        float cx = L[far], cy = L[NN+far], cz = L[2*NN+far];
        float bv = -1.f; int bi = 0;
#pragma unroll
        for (int j = 0; j < 8; ++j) {
            float dx = px[j] - cx;
            float dy = py[j] - cy;
            float dz = pz[j] - cz;
            float d  = __fmaf_rn(dz, dz, __fmaf_rn(dy, dy, __fmul_rn(dx, dx)));
            float nd = fminf(pd[j], d);
            pd[j] = nd;
            if (nd > bv) { bv = nd; bi = j*1024 + t; }  // strict > keeps first idx
        }
#pragma unroll
        for (int off = 16; off; off >>= 1) {
            float v2 = __shfl_down_sync(0xffffffffu, bv, off);
            int   i2 = __shfl_down_sync(0xffffffffu, bi, off);
            amax2(bv, bi, v2, i2);
        }
        if (lane == 0) { swv[wid] = bv; swi[wid] = bi; }
        __syncthreads();
        if (wid == 0) {
            bv = swv[lane]; bi = swi[lane];
#pragma unroll
            for (int off = 16; off; off >>= 1) {
                float v2 = __shfl_down_sync(0xffffffffu, bv, off);
                int   i2 = __shfl_down_sync(0xffffffffu, bi, off);
                amax2(bv, bi, v2, i2);
            }
            if (lane == 0) s_far = bi;
        }
        __syncthreads();
    }
}

// ---------------- K2: y = W_res @ fea + b (writes yT, feaT) ---------------
__global__ void __launch_bounds__(256) k_gemm(const float* __restrict__ fea,
                                              const float* __restrict__ Wres,
                                              const float* __restrict__ bres) {
    __shared__ float sW[CC*CC];
    int b = blockIdx.y;
    int base = blockIdx.x * 256;
    int tid = threadIdx.x;
    for (int i = tid; i < CC*CC; i += 256) sW[i] = Wres[i];
    __syncthreads();
    int ogrp = tid >> 6, nl = tid & 63;
    int o0 = ogrp * 16;
    float acc[4][16];
#pragma unroll
    for (int j = 0; j < 4; ++j)
#pragma unroll
        for (int q = 0; q < 16; ++q) acc[j][q] = 0.f;
    const float* F  = fea + (size_t)b*CC*NN;
    float* FT = g_feaT + (size_t)b*NN*CC;
    for (int c = 0; c < CC; ++c) {
        float f0 = F[(size_t)c*NN + base + nl];
        float f1 = F[(size_t)c*NN + base + 64 + nl];
        float f2 = F[(size_t)c*NN + base + 128 + nl];
        float f3 = F[(size_t)c*NN + base + 192 + nl];
        if (ogrp == 0) {
            FT[(size_t)(base+nl)*CC + c]     = f0;
            FT[(size_t)(base+64+nl)*CC + c]  = f1;
            FT[(size_t)(base+128+nl)*CC + c] = f2;
            FT[(size_t)(base+192+nl)*CC + c] = f3;
        }
#pragma unroll
        for (int q = 0; q < 16; ++q) {
            float w = sW[(o0+q)*CC + c];            // warp-broadcast LDS
            acc[0][q] = fmaf(w, f0, acc[0][q]);
            acc[1][q] = fmaf(w, f1, acc[1][q]);
            acc[2][q] = fmaf(w, f2, acc[2][q]);
            acc[3][q] = fmaf(w, f3, acc[3][q]);
        }
    }
    float* YT = g_yT + (size_t)b*NN*CC;
#pragma unroll
    for (int j = 0; j < 4; ++j) {
        int n = base + j*64 + nl;
        float4* dst = reinterpret_cast<float4*>(YT + (size_t)n*CC + o0);
#pragma unroll
        for (int q4 = 0; q4 < 4; ++q4) {
            float4 v;
            v.x = acc[j][q4*4+0] + bres[o0+q4*4+0];
            v.y = acc[j][q4*4+1] + bres[o0+q4*4+1];
            v.z = acc[j][q4*4+2] + bres[o0+q4*4+2];
            v.w = acc[j][q4*4+3] + bres[o0+q4*4+3];
            dst[q4] = v;
        }
    }
}

// ---------------- K3: BN batch statistics ---------------------------------
__global__ void k_stats() {
    int tid = threadIdx.x;
    int ch = tid & 63, grp = tid >> 6;
    size_t rowbase = (size_t)blockIdx.x * 512;
    float s = 0.f, s2 = 0.f;
    for (int i = grp; i < 512; i += 4) {
        float v = g_yT[(rowbase + i)*CC + ch];
        s += v; s2 = fmaf(v, v, s2);
    }
    __shared__ float sh[256], sh2[256];
    sh[tid] = s; sh2[tid] = s2;
    __syncthreads();
    if (grp == 0) {
        s  = sh[ch]  + sh[ch+64]  + sh[ch+128]  + sh[ch+192];
        s2 = sh2[ch] + sh2[ch+64] + sh2[ch+128] + sh2[ch+192];
        atomicAdd(&g_sum[ch], s);
        atomicAdd(&g_sq[ch], s2);
    }
}

__global__ void k_final(const float* __restrict__ gamma, const float* __restrict__ beta) {
    int c = threadIdx.x;
    if (c < CC) {
        float cnt  = (float)(BB*NN);
        float mean = g_sum[c] / cnt;
        float var  = g_sq[c] / cnt - mean*mean;
        float a    = gamma[c] / sqrtf(var + 1e-5f);
        g_a[c] = a;
        g_c[c] = beta[c] - mean * a;
    }
}

// ---------------- K4: ball query + semantic offset + node_loc -------------
__global__ void k_offset(const float* __restrict__ loc, const float* __restrict__ Woff,
                         float* __restrict__ out_off) {
    __shared__ int sel[8][64];
    int warp = threadIdx.x >> 5, lane = threadIdx.x & 31;
    int id = blockIdx.x * 8 + warp;
    int b = id >> 6, s = id & 63;
    const float* L = loc + (size_t)b*3*NN;
    int nidx = g_fidx[id];
    float fx = L[nidx], fy = L[NN+nidx], fz = L[2*NN+nidx];
    float fs2 = __fmaf_rn(fz, fz, __fmaf_rn(fy, fy, __fmul_rn(fx, fx)));
    const float r2 = (float)(0.3*0.3);
    int cnt = 0;
    for (int basei = 0; basei < NN && cnt < 64; basei += 32) {
        int n = basei + lane;
        float x = L[n], y = L[NN+n], z = L[2*NN+n];
        float dot = __fmaf_rn(fz, z, __fmaf_rn(fy, y, __fmul_rn(fx, x)));
        float ps2 = __fmaf_rn(z, z, __fmaf_rn(y, y, __fmul_rn(x, x)));
        float d   = __fadd_rn(__fadd_rn(__fmul_rn(-2.f, dot), fs2), ps2);
        bool ok = !(d > r2);
        unsigned m = __ballot_sync(0xffffffffu, ok);
        int pos = cnt + __popc(m & ((1u << lane) - 1u));
        if (ok && pos < 64) sel[warp][pos] = n;
        cnt += __popc(m);
    }
    if (cnt > 64) cnt = 64;
    __syncwarp();
    for (int k = cnt + lane; k < 64; k += 32) sel[warp][k] = sel[warp][0];
    __syncwarp();

    const float* FT = g_feaT + (size_t)b*NN*CC;
    float fA = FT[(size_t)nidx*CC + lane];
    float fB = FT[(size_t)nidx*CC + 32 + lane];
    float w0A = Woff[lane],     w0B = Woff[32+lane];
    float w1A = Woff[64+lane],  w1B = Woff[96+lane];
    float w2A = Woff[128+lane], w2B = Woff[160+lane];
    float a0 = 0.f, a1 = 0.f, a2 = 0.f;
    for (int k = 0; k < 64; ++k) {
        int idx = sel[warp][k];
        float gA = FT[(size_t)idx*CC + lane]      - fA;   // coalesced 256B gathers
        float gB = FT[(size_t)idx*CC + 32 + lane] - fB;
        float s0 = fmaf(w0B, gB, w0A*gA);
        float s1 = fmaf(w1B, gB, w1A*gA);
        float s2 = fmaf(w2B, gB, w2A*gA);
#pragma unroll
        for (int off = 16; off; off >>= 1) {
            s0 += __shfl_xor_sync(0xffffffffu, s0, off);
            s1 += __shfl_xor_sync(0xffffffffu, s1, off);
            s2 += __shfl_xor_sync(0xffffffffu, s2, off);
        }
        float gx = L[idx] - fx, gy = L[NN+idx] - fy, gz = L[2*NN+idx] - fz;
        a0 = fmaf(tanhf(s0), gx, a0);
        a1 = fmaf(tanhf(s1), gy, a1);
        a2 = fmaf(tanhf(s2), gz, a2);
    }
    if (lane == 0) {
        float o0 = a0 * (1.f/64.f), o1 = a1 * (1.f/64.f), o2 = a2 * (1.f/64.f);
        out_off[b*3*SS + 0*SS + s] = o0;
        out_off[b*3*SS + 1*SS + s] = o1;
        out_off[b*3*SS + 2*SS + s] = o2;
        g_nodeloc[id*3+0] = fx + o0;
        g_nodeloc[id*3+1] = fy + o1;
        g_nodeloc[id*3+2] = fz + o2;
    }
}

// ---------------- K5: 64-nearest radix select + node_fea ------------------
__global__ void __launch_bounds__(256) k_select(const float* __restrict__ loc,
                                                float* __restrict__ out_nf) {
    __shared__ unsigned skey[NN];     // 32KB sortable keys
    __shared__ int hist[256];
    __shared__ int sel[64];
    __shared__ int eq[128];
    __shared__ int scnt, eqcnt;
    __shared__ unsigned sprefix;
    __shared__ int sk;
    __shared__ float smx[256], smn[256];
    int id = blockIdx.x;
    int b = id >> 6, s = id & 63;
    int tid = threadIdx.x;
    const float* L = loc + (size_t)b*3*NN;
    float nx = g_nodeloc[id*3], ny = g_nodeloc[id*3+1], nz = g_nodeloc[id*3+2];
    float ns2 = __fmaf_rn(nz, nz, __fmaf_rn(ny, ny, __fmul_rn(nx, nx)));
    for (int n = tid; n < NN; n += 256) {
        float x = L[n], y = L[NN+n], z = L[2*NN+n];
        float dot = __fmaf_rn(nz, z, __fmaf_rn(ny, y, __fmul_rn(nx, x)));
        float ps2 = __fmaf_rn(z, z, __fmaf_rn(y, y, __fmul_rn(x, x)));
        float d   = __fadd_rn(__fadd_rn(__fmul_rn(-2.f, dot), ns2), ps2);
        unsigned u = __float_as_uint(d);
        skey[n] = (u & 0x80000000u) ? ~u : (u | 0x80000000u);  // order-preserving
    }
    if (tid == 0) { sprefix = 0u; sk = 64; scnt = 0; eqcnt = 0; }
    __syncthreads();
    for (int shift = 24; shift >= 0; shift -= 8) {
        for (int i = tid; i < 256; i += 256) hist[i] = 0;
        __syncthreads();
        unsigned hm = (shift == 24) ? 0u : (0xFFFFFFFFu << (shift + 8));
        unsigned pref = sprefix;
        for (int n = tid; n < NN; n += 256) {
            unsigned key = skey[n];
            if ((key & hm) == pref) atomicAdd(&hist[(key >> shift) & 255], 1);
        }
        __syncthreads();
        if (tid == 0) {
            int k = sk, cum = 0; unsigned bin = 0;
            for (; bin < 256u; ++bin) {
                int h = hist[bin];
                if (cum + h >= k) { sk = k - cum; break; }
                cum += h;
            }
            sprefix = pref | (bin << shift);
        }
        __syncthreads();
    }
    unsigned T = sprefix;  // key of the 64th smallest
    for (int n = tid; n < NN; n += 256) {
        unsigned key = skey[n];
        if (key < T)       { int p = atomicAdd(&scnt, 1); sel[p] = n; }
        else if (key == T) { int p = atomicAdd(&eqcnt, 1); if (p < 128) eq[p] = n; }
    }
    __syncthreads();
    int need = 64 - scnt;
    if (eqcnt == need) {
        if (tid < need) sel[scnt + tid] = eq[tid];
    } else if (tid == 0) {
        // rare exact-tie overflow: stable (smallest-index) fill
        int p = scnt;
        for (int n = 0; n < NN && p < 64; ++n)
            if (skey[n] == T) sel[p++] = n;
    }
    __syncthreads();

    // node_fea: per-channel max/min over the 64 selected samples, then BN+relu
    int ch = tid & 63, grp = tid >> 6;
    float mx = -CUDART_INF_F, mn = CUDART_INF_F;
    const float* YT = g_yT + (size_t)b*NN*CC;
    for (int k = grp; k < 64; k += 4) {
        float v = YT[(size_t)sel[k]*CC + ch];   // coalesced 256B rows
        mx = fmaxf(mx, v); mn = fminf(mn, v);
    }
    smx[tid] = mx; smn[tid] = mn;
    __syncthreads();
    if (grp == 0) {
        mx = fmaxf(fmaxf(smx[ch], smx[ch+64]), fmaxf(smx[ch+128], smx[ch+192]));
        mn = fminf(fminf(smn[ch], smn[ch+64]), fminf(smn[ch+128], smn[ch+192]));
        float a = g_a[ch], c = g_c[ch];
        float m = (a >= 0.f) ? mx : mn;      // relu(a*y+c) monotone in y by sign(a)
        float val = fmaxf(fmaf(a, m, c), 0.f);
        out_nf[(size_t)b*CC*SS + ch*SS + s] = val;
    }
}

// ---------------- K6: copy input fea into output channels 0..63 -----------
__global__ void k_copy(const float* __restrict__ fea, float* __restrict__ out) {
    size_t i = (size_t)blockIdx.x * 256 + threadIdx.x;   // float4 index
    const size_t per = (size_t)CC*NN/4;                  // per-batch float4 count
    size_t b = i / per, r = i % per;
    reinterpret_cast<float4*>(out)[b*(2*per) + r] =
        reinterpret_cast<const float4*>(fea)[i];
}

// ---------------- K7: 3-NN interpolation into output channels 64..127 -----
__global__ void __launch_bounds__(256) k_upsample(const float* __restrict__ loc,
                                                  const float* __restrict__ nf,
                                                  float* __restrict__ out) {
    __shared__ float snx[SS], sny[SS], snz[SS], sns[SS];
    __shared__ float snf[CC*SS];
    int b = blockIdx.y;
    int tid = threadIdx.x;
    int n = blockIdx.x * 256 + tid;
    if (tid < SS) {
        float x = g_nodeloc[(b*SS+tid)*3];
        float y = g_nodeloc[(b*SS+tid)*3+1];
        float z = g_nodeloc[(b*SS+tid)*3+2];
        snx[tid] = x; sny[tid] = y; snz[tid] = z;
        sns[tid] = __fmaf_rn(z, z, __fmaf_rn(y, y, __fmul_rn(x, x)));
    }
    for (int i = tid; i < CC*SS; i += 256) snf[i] = nf[(size_t)b*CC*SS + i];
    __syncthreads();
    const float* L = loc + (size_t)b*3*NN;
    float x = L[n], y = L[NN+n], z = L[2*NN+n];
    float ps2 = __fmaf_rn(z, z, __fmaf_rn(y, y, __fmul_rn(x, x)));
    float d0 = CUDART_INF_F, d1 = CUDART_INF_F, d2 = CUDART_INF_F;
    int i0 = 0, i1 = 0, i2 = 0;
#pragma unroll 4
    for (int sj = 0; sj < SS; ++sj) {
        float dot = __fmaf_rn(snz[sj], z, __fmaf_rn(sny[sj], y, __fmul_rn(snx[sj], x)));
        float d   = __fadd_rn(__fadd_rn(__fmul_rn(-2.f, dot), ps2), sns[sj]);
        if (d < d0)      { d2 = d1; i2 = i1; d1 = d0; i1 = i0; d0 = d; i0 = sj; }
        else if (d < d1) { d2 = d1; i2 = i1; d1 = d;  i1 = sj; }
        else if (d < d2) { d2 = d;  i2 = sj; }
    }
    d0 = fmaxf(d0, 1e-10f); d1 = fmaxf(d1, 1e-10f); d2 = fmaxf(d2, 1e-10f);
    float w0 = 1.f/d0, w1 = 1.f/d1, w2 = 1.f/d2;
    float ws = (w0 + w1) + w2;
    w0 /= ws; w1 /= ws; w2 /= ws;
    float* O = out + ((size_t)b*2*CC + CC)*NN + n;
    for (int c = 0; c < CC; ++c) {
        float v = fmaf(w2, snf[c*SS+i2], fmaf(w1, snf[c*SS+i1], w0*snf[c*SS+i0]));
        O[(size_t)c*NN] = v;
    }
}

extern "C" void kernel_launch(void* const* d_in, const int* in_sizes, int n_in,
                              void* d_out, int out_size) {
    const float* fea   = (const float*)d_in[0];
    const float* loc   = (const float*)d_in[1];
    const float* Woff  = (const float*)d_in[2];
    const float* Wres  = (const float*)d_in[3];
    const float* bres  = (const float*)d_in[4];
    const float* gamma = (const float*)d_in[5];
    const float* beta  = (const float*)d_in[6];
    float* out = (float*)d_out;
    float* out_nf  = out + (size_t)BB*2*CC*NN;          // node_fea block
    float* out_off = out_nf + (size_t)BB*CC*SS;         // node_offset block

    k_zero<<<1, 64>>>();
    k_fps<<<BB, 1024>>>(loc);
    k_gemm<<<dim3(32, BB), 256>>>(fea, Wres, bres);
    k_stats<<<512, 256>>>();
    k_final<<<1, 64>>>(gamma, beta);
    k_offset<<<BB*SS/8, 256>>>(loc, Woff, out_off);
    k_select<<<BB*SS, 256>>>(loc, out_nf);
    k_copy<<<(unsigned)((size_t)BB*CC*NN/4/256), 256>>>(fea, out);
    k_upsample<<<dim3(NN/256, BB), 256>>>(loc, out_nf, out);
}